// round 1
// baseline (speedup 1.0000x reference)
#include <cuda_runtime.h>

// Problem constants
#define Bn 2
#define Ln 16
#define Cn 16
#define Hn 64
#define Wn 64
#define HW (Hn * Wn)            // 4096

// Scratch (device globals; no allocation allowed)
__device__ float g_imgT[Bn * Ln * HW * Cn];   // images transposed to (B,L,H,W,C): 8 MB
__device__ float g_cum[Bn * Ln * 2 * HW];     // cumsum of flows over L: 1 MB

// ---------------------------------------------------------------------------
// Kernel 1: transpose images (B,L,C,H,W) -> (B,L,H,W,C)
// One thread per (b,l,h,w); reads 16 strided-but-warp-coalesced floats,
// writes 64 contiguous bytes.
// ---------------------------------------------------------------------------
__global__ void transpose_kernel(const float* __restrict__ images) {
    int t = blockIdx.x * blockDim.x + threadIdx.x;   // 0 .. B*L*HW-1
    if (t >= Bn * Ln * HW) return;
    int hw = t & (HW - 1);
    int bl = t >> 12;                                 // b*L + l

    const float* src = images + (size_t)bl * Cn * HW + hw;
    float v[Cn];
#pragma unroll
    for (int c = 0; c < Cn; c++) v[c] = src[(size_t)c * HW];

    float4* dst = reinterpret_cast<float4*>(g_imgT + ((size_t)t << 4));
#pragma unroll
    for (int q = 0; q < 4; q++)
        dst[q] = make_float4(v[4 * q + 0], v[4 * q + 1], v[4 * q + 2], v[4 * q + 3]);
}

// ---------------------------------------------------------------------------
// Kernel 2: cumulative sum of flows over L.
// One thread per (b, d, h, w); d in {0,1}.
// ---------------------------------------------------------------------------
__global__ void cumsum_kernel(const float* __restrict__ flows) {
    int t = blockIdx.x * blockDim.x + threadIdx.x;   // 0 .. B*2*HW-1
    if (t >= Bn * 2 * HW) return;
    int hw = t & (HW - 1);
    int d  = (t >> 12) & 1;
    int b  = t >> 13;

    float acc = 0.0f;
#pragma unroll
    for (int l = 0; l < Ln; l++) {
        size_t idx = (((size_t)(b * Ln + l) * 2 + d) * HW) + hw;
        acc += flows[idx];
        g_cum[idx] = acc;
    }
}

// ---------------------------------------------------------------------------
// Kernel 3: main. One thread per (b,i,h,w). For each j<=i: wrap-x grid,
// bilinear gather 16 channels (4 corners x 4 float4), accumulate.
// ---------------------------------------------------------------------------
__global__ void __launch_bounds__(256) gridsample_pscan_kernel(float* __restrict__ out) {
    int t = blockIdx.x * blockDim.x + threadIdx.x;   // 0 .. B*L*HW-1
    if (t >= Bn * Ln * HW) return;
    int hw = t & (HW - 1);
    int bi = t >> 12;            // b*L + i
    int i  = bi & (Ln - 1);
    int b  = bi >> 4;
    int w  = hw & (Wn - 1);
    int h  = hw >> 6;

    const float gxb = ((float)w + 0.5f) * (2.0f / Wn) - 1.0f;
    const float gyb = ((float)h + 0.5f) * (2.0f / Hn) - 1.0f;

    const float* cumb = g_cum + (size_t)b * Ln * 2 * HW;
    const float cix = cumb[(size_t)(i * 2 + 0) * HW + hw];
    const float ciy = cumb[(size_t)(i * 2 + 1) * HW + hw];

    const float* imgb = g_imgT + (size_t)b * Ln * HW * Cn;

    float acc[Cn];
#pragma unroll
    for (int c = 0; c < Cn; c++) acc[c] = 0.0f;

    for (int j = 0; j <= i; j++) {
        float gx = gxb + cix - cumb[(size_t)(j * 2 + 0) * HW + hw];
        float gy = gyb + ciy - cumb[(size_t)(j * 2 + 1) * HW + hw];

        // gx = remainder(gx + 1, 2) - 1   (result in [-1, 1))
        float tt = gx + 1.0f;
        tt -= floorf(tt * 0.5f) * 2.0f;
        gx = tt - 1.0f;

        float ix = (gx + 1.0f) * (0.5f * Wn) - 0.5f;
        float iy = (gy + 1.0f) * (0.5f * Hn) - 0.5f;

        float x0f = floorf(ix), y0f = floorf(iy);
        float wx = ix - x0f,    wy = iy - y0f;
        int x0 = (int)x0f, y0 = (int)y0f;
        int x1 = x0 + 1,   y1 = y0 + 1;

        bool vx0 = (x0 >= 0) & (x0 < Wn);
        bool vx1 = (x1 >= 0) & (x1 < Wn);
        bool vy0 = (y0 >= 0) & (y0 < Hn);
        bool vy1 = (y1 >= 0) & (y1 < Hn);

        int cx0 = min(max(x0, 0), Wn - 1);
        int cx1 = min(max(x1, 0), Wn - 1);
        int cy0 = min(max(y0, 0), Hn - 1);
        int cy1 = min(max(y1, 0), Hn - 1);

        float w00 = (vx0 && vy0) ? (1.0f - wx) * (1.0f - wy) : 0.0f;
        float w01 = (vx1 && vy0) ? wx * (1.0f - wy)          : 0.0f;
        float w10 = (vx0 && vy1) ? (1.0f - wx) * wy          : 0.0f;
        float w11 = (vx1 && vy1) ? wx * wy                   : 0.0f;

        const float4* p00 = reinterpret_cast<const float4*>(imgb + (((size_t)j * HW + cy0 * Wn + cx0) << 4));
        const float4* p01 = reinterpret_cast<const float4*>(imgb + (((size_t)j * HW + cy0 * Wn + cx1) << 4));
        const float4* p10 = reinterpret_cast<const float4*>(imgb + (((size_t)j * HW + cy1 * Wn + cx0) << 4));
        const float4* p11 = reinterpret_cast<const float4*>(imgb + (((size_t)j * HW + cy1 * Wn + cx1) << 4));

#pragma unroll
        for (int q = 0; q < 4; q++) {
            float4 v00 = p00[q];
            float4 v01 = p01[q];
            float4 v10 = p10[q];
            float4 v11 = p11[q];
            acc[4 * q + 0] += w00 * v00.x + w01 * v01.x + w10 * v10.x + w11 * v11.x;
            acc[4 * q + 1] += w00 * v00.y + w01 * v01.y + w10 * v10.y + w11 * v11.y;
            acc[4 * q + 2] += w00 * v00.z + w01 * v01.z + w10 * v10.z + w11 * v11.z;
            acc[4 * q + 3] += w00 * v00.w + w01 * v01.w + w10 * v10.w + w11 * v11.w;
        }
    }

    // out[(b*L+i)*C + c][hw]
    float* op = out + (size_t)bi * Cn * HW + hw;
#pragma unroll
    for (int c = 0; c < Cn; c++) op[(size_t)c * HW] = acc[c];
}

extern "C" void kernel_launch(void* const* d_in, const int* in_sizes, int n_in,
                              void* d_out, int out_size) {
    const float* flows  = (const float*)d_in[0];   // (B,L,2,H,W)
    const float* images = (const float*)d_in[1];   // (B,L,C,H,W)
    float* out = (float*)d_out;                    // (B,L,C,H,W)

    const int nBLHW = Bn * Ln * HW;   // 131072
    transpose_kernel<<<(nBLHW + 255) / 256, 256>>>(images);
    cumsum_kernel<<<(Bn * 2 * HW + 255) / 256, 256>>>(flows);
    gridsample_pscan_kernel<<<(nBLHW + 255) / 256, 256>>>(out);
}

// round 3
// speedup vs baseline: 2.6861x; 2.6861x over previous
#include <cuda_runtime.h>

// Problem constants
#define Bn 2
#define Ln 16
#define Cn 16
#define Hn 64
#define Wn 64
#define HW (Hn * Wn)            // 4096

// Scratch (device global; no allocation allowed)
__device__ float g_imgT[Bn * Ln * HW * Cn];   // images transposed to (B,L,H,W,C): 8 MB

// ---------------------------------------------------------------------------
// Kernel 1: transpose images (B,L,C,H,W) -> (B,L,H,W,C).
// One thread per 2 adjacent pixels: 16 float2 channel loads (coalesced),
// 8 float4 stores (256B contiguous per thread).
// ---------------------------------------------------------------------------
__global__ void __launch_bounds__(256) transpose_kernel(const float* __restrict__ images) {
    int t = blockIdx.x * blockDim.x + threadIdx.x;   // 0 .. B*L*HW/2-1
    if (t >= Bn * Ln * HW / 2) return;
    int hw2 = t & (HW / 2 - 1);       // pixel-pair index
    int bl  = t >> 11;                // b*L + l

    const float2* src = reinterpret_cast<const float2*>(images + (size_t)bl * Cn * HW) + hw2;
    float2 v[Cn];
#pragma unroll
    for (int c = 0; c < Cn; c++) v[c] = src[(size_t)c * (HW / 2)];

    float4* dst = reinterpret_cast<float4*>(g_imgT + ((size_t)(bl * HW + 2 * hw2) << 4));
#pragma unroll
    for (int q = 0; q < 4; q++)
        dst[q] = make_float4(v[4 * q + 0].x, v[4 * q + 1].x, v[4 * q + 2].x, v[4 * q + 3].x);
#pragma unroll
    for (int q = 0; q < 4; q++)
        dst[4 + q] = make_float4(v[4 * q + 0].y, v[4 * q + 1].y, v[4 * q + 2].y, v[4 * q + 3].y);
}

// ---------------------------------------------------------------------------
// Kernel 2: main. 4 lanes per pixel, each lane owns a float4 of channels.
// A warp covers 8 adjacent-w pixels -> each corner gather is one LDG.128
// spanning 512B contiguous (4 wavefronts, full sector use).
// Relative displacement rel(i,j) = cum_i - cum_j is built on the fly by
// iterating j = i .. 0 and accumulating flow[j] after each sample.
// ---------------------------------------------------------------------------
__global__ void __launch_bounds__(256) gridsample_pscan_kernel(const float* __restrict__ flows,
                                                               float* __restrict__ out) {
    int t = blockIdx.x * blockDim.x + threadIdx.x;   // 0 .. B*L*HW*4-1
    if (t >= Bn * Ln * HW * 4) return;
    int cg = t & 3;              // channel group (4 channels)
    int pg = t >> 2;             // pixel-global: b*L*HW + hw
    int hw = pg & (HW - 1);
    int bi = pg >> 12;           // b*L + i
    int i  = bi & (Ln - 1);
    int b  = bi >> 4;
    int w  = hw & (Wn - 1);
    int h  = hw >> 6;

    const float gxb = ((float)w + 0.5f) * (2.0f / Wn) - 1.0f;
    const float gyb = ((float)h + 0.5f) * (2.0f / Hn) - 1.0f;

    const float* flowb = flows + (size_t)b * Ln * 2 * HW + hw;   // + (j*2+d)*HW
    const float* imgb  = g_imgT + (size_t)b * Ln * HW * Cn + cg * 4;

    float relx = 0.0f, rely = 0.0f;   // cum_i - cum_j ; zero at j = i
    float acc0 = 0.0f, acc1 = 0.0f, acc2 = 0.0f, acc3 = 0.0f;

    for (int j = i; j >= 0; --j) {
        float gx = gxb + relx;
        float gy = gyb + rely;

        // gx = remainder(gx + 1, 2) - 1   (floored mod, result in [-1, 1))
        float tt = gx + 1.0f;
        tt -= floorf(tt * 0.5f) * 2.0f;
        gx = tt - 1.0f;

        float ix = (gx + 1.0f) * (0.5f * Wn) - 0.5f;
        float iy = (gy + 1.0f) * (0.5f * Hn) - 0.5f;

        float x0f = floorf(ix), y0f = floorf(iy);
        float wx = ix - x0f,    wy = iy - y0f;
        int x0 = (int)x0f, y0 = (int)y0f;
        int x1 = x0 + 1,   y1 = y0 + 1;

        bool vx0 = (x0 >= 0) & (x0 < Wn);
        bool vx1 = (x1 >= 0) & (x1 < Wn);
        bool vy0 = (y0 >= 0) & (y0 < Hn);
        bool vy1 = (y1 >= 0) & (y1 < Hn);

        int cx0 = min(max(x0, 0), Wn - 1);
        int cx1 = min(max(x1, 0), Wn - 1);
        int cy0 = min(max(y0, 0), Hn - 1);
        int cy1 = min(max(y1, 0), Hn - 1);

        float w00 = (vx0 && vy0) ? (1.0f - wx) * (1.0f - wy) : 0.0f;
        float w01 = (vx1 && vy0) ? wx * (1.0f - wy)          : 0.0f;
        float w10 = (vx0 && vy1) ? (1.0f - wx) * wy          : 0.0f;
        float w11 = (vx1 && vy1) ? wx * wy                   : 0.0f;

        const float4 v00 = *reinterpret_cast<const float4*>(imgb + (((size_t)j * HW + cy0 * Wn + cx0) << 4));
        const float4 v01 = *reinterpret_cast<const float4*>(imgb + (((size_t)j * HW + cy0 * Wn + cx1) << 4));
        const float4 v10 = *reinterpret_cast<const float4*>(imgb + (((size_t)j * HW + cy1 * Wn + cx0) << 4));
        const float4 v11 = *reinterpret_cast<const float4*>(imgb + (((size_t)j * HW + cy1 * Wn + cx1) << 4));

        acc0 += w00 * v00.x + w01 * v01.x + w10 * v10.x + w11 * v11.x;
        acc1 += w00 * v00.y + w01 * v01.y + w10 * v10.y + w11 * v11.y;
        acc2 += w00 * v00.z + w01 * v01.z + w10 * v10.z + w11 * v11.z;
        acc3 += w00 * v00.w + w01 * v01.w + w10 * v10.w + w11 * v11.w;

        // advance rel to (i, j-1): rel += flow[j]
        relx += flowb[(size_t)(j * 2 + 0) * HW];
        rely += flowb[(size_t)(j * 2 + 1) * HW];
    }

    // out[b,i,c,h,w]: this lane owns channels 4*cg .. 4*cg+3
    float* op = out + (size_t)bi * Cn * HW + (size_t)(cg * 4) * HW + hw;
    op[0 * HW] = acc0;
    op[1 * HW] = acc1;
    op[2 * HW] = acc2;
    op[3 * HW] = acc3;
}

extern "C" void kernel_launch(void* const* d_in, const int* in_sizes, int n_in,
                              void* d_out, int out_size) {
    const float* flows  = (const float*)d_in[0];   // (B,L,2,H,W)
    const float* images = (const float*)d_in[1];   // (B,L,C,H,W)
    float* out = (float*)d_out;                    // (B,L,C,H,W)

    const int nT = Bn * Ln * HW / 2;       // 65536 transpose threads
    transpose_kernel<<<(nT + 255) / 256, 256>>>(images);

    const int nM = Bn * Ln * HW * 4;       // 524288 main threads
    gridsample_pscan_kernel<<<(nM + 255) / 256, 256>>>(flows, out);
}

// round 5
// speedup vs baseline: 3.0093x; 1.1203x over previous
#include <cuda_runtime.h>

// Problem constants
#define Bn 2
#define Ln 16
#define Cn 16
#define Hn 64
#define Wn 64
#define HW (Hn * Wn)            // 4096

// Padded transposed image: entry = 16 channels (64B).
// Stored rows cover y = -1..65 (PR=67), cols cover x = -1..64 (PC=66).
// Border entries are never written -> stay zero (device globals zero-init).
#define PR 67
#define PC 66
#define PLANE (PR * PC)         // 4422 entries per (b,l)

__device__ float g_imgT[Bn * Ln * PLANE * Cn];   // ~9.06 MB

// ---------------------------------------------------------------------------
// Kernel 1: transpose images (B,L,C,H,W) -> padded (B,L,(H+3),(W+2),C).
// One thread per pixel: 16 coalesced scalar loads, 4 float4 stores (64B).
// ---------------------------------------------------------------------------
__global__ void __launch_bounds__(256) transpose_kernel(const float* __restrict__ images) {
    int t = blockIdx.x * blockDim.x + threadIdx.x;   // 0 .. B*L*HW-1
    if (t >= Bn * Ln * HW) return;
    int hw = t & (HW - 1);
    int bl = t >> 12;
    int w = hw & (Wn - 1);
    int h = hw >> 6;

    const float* src = images + (size_t)bl * Cn * HW + hw;
    float v[Cn];
#pragma unroll
    for (int c = 0; c < Cn; c++) v[c] = src[(size_t)c * HW];

    size_t e = (size_t)bl * PLANE + (size_t)(h + 1) * PC + (w + 1);
    float4* dst = reinterpret_cast<float4*>(g_imgT + e * Cn);
#pragma unroll
    for (int q = 0; q < 4; q++)
        dst[q] = make_float4(v[4 * q + 0], v[4 * q + 1], v[4 * q + 2], v[4 * q + 3]);
}

// ---------------------------------------------------------------------------
// Kernel 2: main. 4 lanes per pixel, each lane owns a float4 of channels.
// Zero-padded image removes all validity masking/clamps: one address per
// sample + 3 constant offsets. iy clamped to [-1,64] (== reference masking).
// rel(i,j) built on the fly iterating j = i..0.
// ---------------------------------------------------------------------------
__global__ void __launch_bounds__(256) gridsample_pscan_kernel(const float* __restrict__ flows,
                                                               float* __restrict__ out) {
    int t = blockIdx.x * blockDim.x + threadIdx.x;   // 0 .. B*L*HW*4-1
    if (t >= Bn * Ln * HW * 4) return;
    int cg = t & 3;              // channel group (4 channels)
    int pg = t >> 2;             // b*L*HW + hw
    int hw = pg & (HW - 1);
    int bi = pg >> 12;           // b*L + i
    int i  = bi & (Ln - 1);
    int b  = bi >> 4;
    int w  = hw & (Wn - 1);
    int h  = hw >> 6;

    // ix = ((gx_wrapped)+1)*32 - 0.5 where gx = gxb + relx, wrap to [-1,1):
    //   u = (w+0.5) + relx*32 ;  ix = u - 64*floor(u/64) - 0.5
    // iy = (gyb + rely + 1)*32 - 0.5 = h + rely*32
    const float uxb = (float)w + 0.5f;
    const float fyb = (float)h;

    const float* flowb = flows + (size_t)b * Ln * 2 * HW + hw;     // + (j*2+d)*HW
    const float* imgb  = g_imgT + (size_t)b * Ln * PLANE * Cn + cg * 4;

    float relx = 0.0f, rely = 0.0f;   // cum_i - cum_j ; zero at j = i
    float acc0 = 0.0f, acc1 = 0.0f, acc2 = 0.0f, acc3 = 0.0f;

#pragma unroll 2
    for (int j = i; j >= 0; --j) {
        // x: wrap into [0,64), then shift by -0.5
        float u  = fmaf(relx, 32.0f, uxb);
        float fq = floorf(u * 0.015625f);           // u/64
        float ix = fmaf(fq, -64.0f, u) - 0.5f;      // in [-0.5, 63.5)
        // y: clamp to [-1, 64] (equivalent to validity masking w/ zero border)
        float iy = fmaf(rely, 32.0f, fyb);
        iy = fminf(fmaxf(iy, -1.0f), 64.0f);

        float x0f = floorf(ix), y0f = floorf(iy);
        float wx = ix - x0f,    wy = iy - y0f;
        int x0 = (int)x0f, y0 = (int)y0f;           // x0 in [-1,63], y0 in [-1,64]

        float wx1 = 1.0f - wx, wy1 = 1.0f - wy;
        float w00 = wx1 * wy1, w01 = wx * wy1, w10 = wx1 * wy, w11 = wx * wy;

        // entry index: j*PLANE + (y0+1)*PC + (x0+1)  -> always in-bounds
        int e = j * PLANE + y0 * PC + x0 + (PC + 1);
        const float* p = imgb + ((size_t)e << 4);

        const float4 v00 = *reinterpret_cast<const float4*>(p);
        const float4 v01 = *reinterpret_cast<const float4*>(p + Cn);
        const float4 v10 = *reinterpret_cast<const float4*>(p + PC * Cn);
        const float4 v11 = *reinterpret_cast<const float4*>(p + (PC + 1) * Cn);

        acc0 += w00 * v00.x + w01 * v01.x + w10 * v10.x + w11 * v11.x;
        acc1 += w00 * v00.y + w01 * v01.y + w10 * v10.y + w11 * v11.y;
        acc2 += w00 * v00.z + w01 * v01.z + w10 * v10.z + w11 * v11.z;
        acc3 += w00 * v00.w + w01 * v01.w + w10 * v10.w + w11 * v11.w;

        // advance rel to (i, j-1): rel += flow[j]
        relx += flowb[(size_t)(j * 2 + 0) * HW];
        rely += flowb[(size_t)(j * 2 + 1) * HW];
    }

    // out[b,i,c,h,w]: this lane owns channels 4*cg .. 4*cg+3
    float* op = out + (size_t)bi * Cn * HW + (size_t)(cg * 4) * HW + hw;
    op[0 * HW] = acc0;
    op[1 * HW] = acc1;
    op[2 * HW] = acc2;
    op[3 * HW] = acc3;
}

extern "C" void kernel_launch(void* const* d_in, const int* in_sizes, int n_in,
                              void* d_out, int out_size) {
    const float* flows  = (const float*)d_in[0];   // (B,L,2,H,W)
    const float* images = (const float*)d_in[1];   // (B,L,C,H,W)
    float* out = (float*)d_out;                    // (B,L,C,H,W)

    const int nT = Bn * Ln * HW;           // 131072 transpose threads
    transpose_kernel<<<(nT + 255) / 256, 256>>>(images);

    const int nM = Bn * Ln * HW * 4;       // 524288 main threads
    gridsample_pscan_kernel<<<(nM + 255) / 256, 256>>>(flows, out);
}